// round 6
// baseline (speedup 1.0000x reference)
#include <cuda_runtime.h>
#include <cstdint>

// MPS classifier: logits[b] = unit(v_b @ prod_n M_n(b)) @ C^T + log||prod||
// Pair-fused matrices P staged in smem (double-buffered cp.async).
// R6: l-pair-packed table + fma.rn.f32x2 (halves FMA instruction count) and
// asm-volatile shared loads (forces load batching; R5 showed ptxas otherwise
// re-serializes load/use and exposes full LDS latency every l-iteration).
//
// Table layout per pair-step s: for l-pair q in 0..4, h in 0..9, two float4:
//   e=0: (p00[2q][h], p00[2q+1][h], p10[2q][h], p10[2q+1][h])
//   e=1: (p01[2q][h], p01[2q+1][h], p11[2q][h], p11[2q+1][h])
// float4 index = s*100 + (q*2+e)*10 + h.

#define NSITE 783
#define NPAIR 392
#define CHUNK 14             // pairs per chunk
#define NCHUNK 28            // 392 / 14
#define BPB 16               // batches per block (4 warps x 4)
#define THREADS 128
#define NBLOCK 128           // 128 * 16 = 2048 exactly
#define XV 8                 // float4 x-vectors staged per batch per chunk

__device__ float4 g_pmat[NPAIR * 100];

__device__ __forceinline__ void cpasync16(void* dst_smem, const void* src) {
    uint32_t d = (uint32_t)__cvta_generic_to_shared(dst_smem);
    asm volatile("cp.async.cg.shared.global [%0], [%1], 16;" :: "r"(d), "l"(src) : "memory");
}

__device__ __forceinline__ uint64_t pack2(float lo, float hi) {
    uint64_t r;
    asm("mov.b64 %0, {%1, %2};" : "=l"(r) : "r"(__float_as_uint(lo)), "r"(__float_as_uint(hi)));
    return r;
}
__device__ __forceinline__ uint64_t fma2(uint64_t a, uint64_t b, uint64_t c) {
    uint64_t d;
    asm("fma.rn.f32x2 %0, %1, %2, %3;" : "=l"(d) : "l"(a), "l"(b), "l"(c));
    return d;
}
__device__ __forceinline__ float sum2(uint64_t v) {
    uint32_t lo, hi;
    asm("mov.b64 {%0, %1}, %2;" : "=r"(lo), "=r"(hi) : "l"(v));
    return __uint_as_float(lo) + __uint_as_float(hi);
}

// ---------------------------------------------------------------------------
// Precompute pair matrices in the l-pair-packed layout. One block per pair.
// cores_mid layout: [n][l][f][h] -> ((l*2+f)*10 + h), n in [0,783)
// ---------------------------------------------------------------------------
__global__ void prep_pairs_kernel(const float* __restrict__ cm) {
    __shared__ float s1[200];
    __shared__ float s2[200];
    __shared__ float4 sP[100];   // (l,h) -> (p00, p10, p01, p11)
    int j = blockIdx.x;
    int t = threadIdx.x;
    int s2i = 2 * j + 1;
    if (t < 100) {
        const float* p1 = cm + (2 * j) * 200;
        s1[t]       = p1[t];
        s1[t + 100] = p1[t + 100];
        if (s2i < NSITE) {
            const float* p2 = cm + s2i * 200;
            s2[t]       = p2[t];
            s2[t + 100] = p2[t + 100];
        } else {
            #pragma unroll
            for (int q = t; q < 200; q += 100) {
                int l = q / 20;
                int h = q % 10;
                s2[q] = (l == h) ? 1.0f : 0.0f;   // identity pad (D2 = 0)
            }
        }
    }
    __syncthreads();
    if (t < 100) {
        int l = t / 10;
        int h = t % 10;
        float p00 = 0.f, p10 = 0.f, p01 = 0.f, p11 = 0.f;
        #pragma unroll
        for (int k = 0; k < 10; k++) {
            float a1 = s1[l * 20 + k];
            float d1 = s1[l * 20 + 10 + k] - a1;
            float a2 = s2[k * 20 + h];
            float d2 = s2[k * 20 + 10 + h] - a2;
            p00 = fmaf(a1, a2, p00);
            p10 = fmaf(d1, a2, p10);
            p01 = fmaf(a1, d2, p01);
            p11 = fmaf(d1, d2, p11);
        }
        sP[t] = make_float4(p00, p10, p01, p11);
    }
    __syncthreads();
    if (t < 100) {
        int q = t / 20;
        int e = (t / 10) % 2;
        int h = t % 10;
        float4 u0 = sP[(2 * q) * 10 + h];
        float4 u1 = sP[(2 * q + 1) * 10 + h];
        float4 o = (e == 0) ? make_float4(u0.x, u1.x, u0.y, u1.y)
                            : make_float4(u0.z, u1.z, u0.w, u1.w);
        g_pmat[j * 100 + (q * 2 + e) * 10 + h] = o;
    }
}

// ---------------------------------------------------------------------------
// Main chain kernel. 128 threads = 4 warps = 16 batches (1 warp per SMSP).
// Warp w: half 0 (lanes 0-15): va=batch 4w+0, vb=4w+1; half 1: 4w+2, 4w+3.
// Lane h (h<10) owns component h; lanes 10-15 mirror lane 9 (masked).
// ---------------------------------------------------------------------------
__global__ void __launch_bounds__(THREADS, 1) mps_chain_kernel(
    const float* __restrict__ x,      // [2048, 784]
    const float* __restrict__ core0,  // [1, 2, 10]
    const float* __restrict__ cls,    // [10, 10]
    float* __restrict__ out)          // [2048, 10]
{
    __shared__ float4 bufP[2][CHUNK * 100];   // 2 x 22.4 KB
    __shared__ float4 bufX[2][BPB * XV];      // 2 x 2 KB (32 floats/batch)

    const unsigned FULL = 0xffffffffu;
    int tid  = threadIdx.x;
    int lane = tid & 31;
    int warp = tid >> 5;
    int half = lane >> 4;
    int h    = lane & 15;
    int hc   = (h < 10) ? h : 9;
    bool act = (h < 10);

    int base = blockIdx.x * BPB;
    int ia   = warp * 4 + half * 2;
    int ba   = base + ia;
    int bb   = ba + 1;

    auto issue_chunk = [&](int c) {
        int pb = c & 1;
        int nvec = (c == NCHUNK - 1) ? 7 : XV;   // last chunk: 756+28 = 784
        const float4* psrc = g_pmat + c * (CHUNK * 100);
        for (int i = tid; i < CHUNK * 100 + BPB * XV; i += THREADS) {
            if (i < CHUNK * 100) {
                cpasync16(&bufP[pb][i], psrc + i);
            } else {
                int q  = i - CHUNK * 100;
                int bi = q >> 3, vv = q & 7;
                if (vv < nvec) {
                    cpasync16(&bufX[pb][bi * XV + vv],
                              x + (size_t)(base + bi) * 784 + c * (2 * CHUNK) + vv * 4);
                }
            }
        }
        asm volatile("cp.async.commit_group;" ::: "memory");
    };

    // heads
    float t0a = __ldg(x + (size_t)ba * 784);
    float t0b = __ldg(x + (size_t)bb * 784);
    float c0a = __ldg(core0 + hc);
    float c0d = __ldg(core0 + 10 + hc) - c0a;
    float va = fmaf(t0a, c0d, c0a);
    float vb = fmaf(t0b, c0d, c0a);
    int Ka = 0, Kb = 0;

    issue_chunk(0);
    asm volatile("cp.async.wait_group 0;" ::: "memory");
    __syncthreads();

    for (int c = 0; c < NCHUNK; c++) {
        int pb = c & 1;
        if (c + 1 < NCHUNK) issue_chunk(c + 1);

        uint32_t pbase = (uint32_t)__cvta_generic_to_shared(&bufP[pb][0]) + hc * 16u;
        const float* txa = (const float*)(&bufX[pb][ia * XV]);
        const float* txb = (const float*)(&bufX[pb][(ia + 1) * XV]);

        #pragma unroll 1
        for (int jj = 0; jj < CHUNK; jj++) {
            // ---- phase 1: all 10 shared loads, asm-ordered up front ----
            uint64_t A[5], B[5], C[5], D[5];
            uint32_t sa = pbase + (uint32_t)jj * 1600u;
            #pragma unroll
            for (int q = 0; q < 5; q++) {
                asm volatile("ld.shared.v2.u64 {%0, %1}, [%2];"
                             : "=l"(A[q]), "=l"(B[q]) : "r"(sa + q * 320u));
                asm volatile("ld.shared.v2.u64 {%0, %1}, [%2];"
                             : "=l"(C[q]), "=l"(D[q]) : "r"(sa + q * 320u + 160u));
            }

            // identity-padded pair (last of last chunk): t2 reads a stale but
            // finite slot; it multiplies p01 = p11 = 0.
            float t1a = txa[2 * jj + 1], t2a = txa[2 * jj + 2];
            float t1b = txb[2 * jj + 1], t2b = txb[2 * jj + 2];
            uint64_t t1a2 = pack2(t1a, t1a), t2a2 = pack2(t2a, t2a);
            uint64_t t1b2 = pack2(t1b, t1b), t2b2 = pack2(t2b, t2b);
            float ca = t1a * t2a, cb = t1b * t2b;
            uint64_t ca2 = pack2(ca, ca), cb2 = pack2(cb, cb);

            // ---- phase 2: shuffles + packs ----
            uint64_t vla2[5], vlb2[5];
            #pragma unroll
            for (int q = 0; q < 5; q++) {
                float a0 = __shfl_sync(FULL, va, 2 * q,     16);
                float a1 = __shfl_sync(FULL, va, 2 * q + 1, 16);
                float b0 = __shfl_sync(FULL, vb, 2 * q,     16);
                float b1 = __shfl_sync(FULL, vb, 2 * q + 1, 16);
                vla2[q] = pack2(a0, a1);
                vlb2[q] = pack2(b0, b1);
            }

            // ---- phase 3: packed math ----
            uint64_t wa2 = 0, wb2 = 0;
            #pragma unroll
            for (int q = 0; q < 5; q++) {
                uint64_t ma = fma2(t1a2, B[q], A[q]);
                uint64_t mb = fma2(t1b2, B[q], A[q]);
                ma = fma2(t2a2, C[q], ma);
                mb = fma2(t2b2, C[q], mb);
                ma = fma2(ca2, D[q], ma);
                mb = fma2(cb2, D[q], mb);
                wa2 = fma2(vla2[q], ma, wa2);
                wb2 = fma2(vlb2[q], mb, wb2);
            }
            va = sum2(wa2);
            vb = sum2(wb2);
        }

        // exact power-of-2 rescale per batch
        {
            float ssa = act ? va * va : 0.0f;
            float ssb = act ? vb * vb : 0.0f;
            ssa += __shfl_xor_sync(FULL, ssa, 1, 16);
            ssb += __shfl_xor_sync(FULL, ssb, 1, 16);
            ssa += __shfl_xor_sync(FULL, ssa, 2, 16);
            ssb += __shfl_xor_sync(FULL, ssb, 2, 16);
            ssa += __shfl_xor_sync(FULL, ssa, 4, 16);
            ssb += __shfl_xor_sync(FULL, ssb, 4, 16);
            ssa += __shfl_xor_sync(FULL, ssa, 8, 16);
            ssb += __shfl_xor_sync(FULL, ssb, 8, 16);
            int sha = (((__float_as_int(ssa) >> 23) & 0xff) - 127) >> 1;
            int shb = (((__float_as_int(ssb) >> 23) & 0xff) - 127) >> 1;
            Ka += sha;
            Kb += shb;
            va *= __int_as_float((127 - sha) << 23);
            vb *= __int_as_float((127 - shb) << 23);
        }

        if (c + 1 < NCHUNK)
            asm volatile("cp.async.wait_group 0;" ::: "memory");
        __syncthreads();
    }

    // final norm + single log per batch
    float ssa = act ? va * va : 0.0f;
    float ssb = act ? vb * vb : 0.0f;
    ssa += __shfl_xor_sync(FULL, ssa, 1, 16);
    ssb += __shfl_xor_sync(FULL, ssb, 1, 16);
    ssa += __shfl_xor_sync(FULL, ssa, 2, 16);
    ssb += __shfl_xor_sync(FULL, ssb, 2, 16);
    ssa += __shfl_xor_sync(FULL, ssa, 4, 16);
    ssb += __shfl_xor_sync(FULL, ssb, 4, 16);
    ssa += __shfl_xor_sync(FULL, ssa, 8, 16);
    ssb += __shfl_xor_sync(FULL, ssb, 8, 16);
    float na = fmaxf(sqrtf(ssa), 1e-30f);
    float nb = fmaxf(sqrtf(ssb), 1e-30f);
    const float LN2 = 0.69314718055994531f;
    float lna = (float)Ka * LN2 + __logf(na);
    float lnb = (float)Kb * LN2 + __logf(nb);
    va *= (1.0f / na);
    vb *= (1.0f / nb);

    // logits[b,o] = sum_l v_l * cls[o,l] + lognorm   (lane h = class o)
    float cw[10];
    #pragma unroll
    for (int l = 0; l < 10; l++) cw[l] = __ldg(cls + hc * 10 + l);
    float acca = lna, accb = lnb;
    #pragma unroll
    for (int l = 0; l < 10; l++) {
        float vla = __shfl_sync(FULL, va, l, 16);
        float vlb = __shfl_sync(FULL, vb, l, 16);
        acca = fmaf(vla, cw[l], acca);
        accb = fmaf(vlb, cw[l], accb);
    }
    if (act) {
        out[(size_t)ba * 10 + h] = acca;
        out[(size_t)bb * 10 + h] = accb;
    }
}

// ---------------------------------------------------------------------------
extern "C" void kernel_launch(void* const* d_in, const int* in_sizes, int n_in,
                              void* d_out, int out_size) {
    const float* x     = (const float*)d_in[0];  // [2048, 784]
    const float* core0 = (const float*)d_in[1];  // [1, 2, 10]
    const float* cm    = (const float*)d_in[2];  // [783, 10, 2, 10]
    const float* cls   = (const float*)d_in[3];  // [10, 10]
    float* out = (float*)d_out;                  // [2048, 10]

    prep_pairs_kernel<<<NPAIR, 128>>>(cm);
    mps_chain_kernel<<<NBLOCK, THREADS>>>(x, core0, cls, out);
}

// round 7
// speedup vs baseline: 1.1744x; 1.1744x over previous
#include <cuda_runtime.h>
#include <cstdint>

// MPS classifier: logits[b] = unit(v_b @ prod_n M_n(b)) @ C^T + log||prod||
// Pair-fused matrices P staged in smem (double-buffered cp.async).
// R7: fma.rn.f32x2 retry with scheduling freedom restored — plain C++ u64
// vector loads (no asm volatile), fully unrolled step loop (constant smem
// offsets -> ptxas prefetches across steps), u64 operands end-to-end.
//
// Table layout per pair-step s (same as R6): for l-pair q in 0..4, h in 0..9:
//   e=0: (p00[2q][h], p00[2q+1][h], p10[2q][h], p10[2q+1][h])
//   e=1: (p01[2q][h], p01[2q+1][h], p11[2q][h], p11[2q+1][h])
// float4 index = s*100 + (q*2+e)*10 + h.

#define NSITE 783
#define NPAIR 392
#define CHUNK 14             // pairs per chunk
#define NCHUNK 28            // 392 / 14
#define BPB 16               // batches per block (4 warps x 4)
#define THREADS 128
#define NBLOCK 128           // 128 * 16 = 2048 exactly
#define XV 8                 // float4 x-vectors staged per batch per chunk

__device__ float4 g_pmat[NPAIR * 100];

__device__ __forceinline__ void cpasync16(void* dst_smem, const void* src) {
    uint32_t d = (uint32_t)__cvta_generic_to_shared(dst_smem);
    asm volatile("cp.async.cg.shared.global [%0], [%1], 16;" :: "r"(d), "l"(src) : "memory");
}

__device__ __forceinline__ uint64_t pack2(float lo, float hi) {
    uint64_t r;
    asm("mov.b64 %0, {%1, %2};" : "=l"(r) : "r"(__float_as_uint(lo)), "r"(__float_as_uint(hi)));
    return r;
}
__device__ __forceinline__ uint64_t fma2(uint64_t a, uint64_t b, uint64_t c) {
    uint64_t d;
    asm("fma.rn.f32x2 %0, %1, %2, %3;" : "=l"(d) : "l"(a), "l"(b), "l"(c));
    return d;
}
__device__ __forceinline__ float sum2(uint64_t v) {
    uint32_t lo, hi;
    asm("mov.b64 {%0, %1}, %2;" : "=r"(lo), "=r"(hi) : "l"(v));
    return __uint_as_float(lo) + __uint_as_float(hi);
}

// ---------------------------------------------------------------------------
// Precompute pair matrices in the l-pair-packed layout. One block per pair.
// cores_mid layout: [n][l][f][h] -> ((l*2+f)*10 + h), n in [0,783)
// ---------------------------------------------------------------------------
__global__ void prep_pairs_kernel(const float* __restrict__ cm) {
    __shared__ float s1[200];
    __shared__ float s2[200];
    __shared__ float4 sP[100];   // (l,h) -> (p00, p10, p01, p11)
    int j = blockIdx.x;
    int t = threadIdx.x;
    int s2i = 2 * j + 1;
    if (t < 100) {
        const float* p1 = cm + (2 * j) * 200;
        s1[t]       = p1[t];
        s1[t + 100] = p1[t + 100];
        if (s2i < NSITE) {
            const float* p2 = cm + s2i * 200;
            s2[t]       = p2[t];
            s2[t + 100] = p2[t + 100];
        } else {
            #pragma unroll
            for (int q = t; q < 200; q += 100) {
                int l = q / 20;
                int h = q % 10;
                s2[q] = (l == h) ? 1.0f : 0.0f;   // identity pad (D2 = 0)
            }
        }
    }
    __syncthreads();
    if (t < 100) {
        int l = t / 10;
        int h = t % 10;
        float p00 = 0.f, p10 = 0.f, p01 = 0.f, p11 = 0.f;
        #pragma unroll
        for (int k = 0; k < 10; k++) {
            float a1 = s1[l * 20 + k];
            float d1 = s1[l * 20 + 10 + k] - a1;
            float a2 = s2[k * 20 + h];
            float d2 = s2[k * 20 + 10 + h] - a2;
            p00 = fmaf(a1, a2, p00);
            p10 = fmaf(d1, a2, p10);
            p01 = fmaf(a1, d2, p01);
            p11 = fmaf(d1, d2, p11);
        }
        sP[t] = make_float4(p00, p10, p01, p11);
    }
    __syncthreads();
    if (t < 100) {
        int q = t / 20;
        int e = (t / 10) % 2;
        int h = t % 10;
        float4 u0 = sP[(2 * q) * 10 + h];
        float4 u1 = sP[(2 * q + 1) * 10 + h];
        float4 o = (e == 0) ? make_float4(u0.x, u1.x, u0.y, u1.y)
                            : make_float4(u0.z, u1.z, u0.w, u1.w);
        g_pmat[j * 100 + (q * 2 + e) * 10 + h] = o;
    }
}

// ---------------------------------------------------------------------------
// Main chain kernel. 128 threads = 4 warps = 16 batches (1 warp per SMSP).
// Warp w: half 0 (lanes 0-15): va=batch 4w+0, vb=4w+1; half 1: 4w+2, 4w+3.
// Lane h (h<10) owns component h; lanes 10-15 mirror lane 9 (masked).
// ---------------------------------------------------------------------------
__global__ void __launch_bounds__(THREADS, 1) mps_chain_kernel(
    const float* __restrict__ x,      // [2048, 784]
    const float* __restrict__ core0,  // [1, 2, 10]
    const float* __restrict__ cls,    // [10, 10]
    float* __restrict__ out)          // [2048, 10]
{
    __shared__ float4 bufP[2][CHUNK * 100];   // 2 x 22.4 KB
    __shared__ float4 bufX[2][BPB * XV];      // 2 x 2 KB (32 floats/batch)

    const unsigned FULL = 0xffffffffu;
    int tid  = threadIdx.x;
    int lane = tid & 31;
    int warp = tid >> 5;
    int half = lane >> 4;
    int h    = lane & 15;
    int hc   = (h < 10) ? h : 9;
    bool act = (h < 10);

    int base = blockIdx.x * BPB;
    int ia   = warp * 4 + half * 2;
    int ba   = base + ia;
    int bb   = ba + 1;

    auto issue_chunk = [&](int c) {
        int pb = c & 1;
        int nvec = (c == NCHUNK - 1) ? 7 : XV;   // last chunk: 756+28 = 784
        const float4* psrc = g_pmat + c * (CHUNK * 100);
        for (int i = tid; i < CHUNK * 100 + BPB * XV; i += THREADS) {
            if (i < CHUNK * 100) {
                cpasync16(&bufP[pb][i], psrc + i);
            } else {
                int q  = i - CHUNK * 100;
                int bi = q >> 3, vv = q & 7;
                if (vv < nvec) {
                    cpasync16(&bufX[pb][bi * XV + vv],
                              x + (size_t)(base + bi) * 784 + c * (2 * CHUNK) + vv * 4);
                }
            }
        }
        asm volatile("cp.async.commit_group;" ::: "memory");
    };

    // heads
    float t0a = __ldg(x + (size_t)ba * 784);
    float t0b = __ldg(x + (size_t)bb * 784);
    float c0a = __ldg(core0 + hc);
    float c0d = __ldg(core0 + 10 + hc) - c0a;
    float va = fmaf(t0a, c0d, c0a);
    float vb = fmaf(t0b, c0d, c0a);
    int Ka = 0, Kb = 0;

    issue_chunk(0);
    asm volatile("cp.async.wait_group 0;" ::: "memory");
    __syncthreads();

    for (int c = 0; c < NCHUNK; c++) {
        int pb = c & 1;
        if (c + 1 < NCHUNK) issue_chunk(c + 1);

        // u64-pair view of this chunk's table, offset to this lane's h.
        const ulonglong2* Ph = (const ulonglong2*)(&bufP[pb][0]) + hc;
        const float* txa = (const float*)(&bufX[pb][ia * XV]);
        const float* txb = (const float*)(&bufX[pb][(ia + 1) * XV]);

        #pragma unroll
        for (int jj = 0; jj < CHUNK; jj++) {
            // ---- loads: plain C++ (schedulable / hoistable by ptxas) ----
            // entry (q*2+e)*10+h at float4 granularity == ulonglong2 index
            const ulonglong2* p = Ph + jj * 100;
            ulonglong2 AB0 = p[0],  CD0 = p[10];
            ulonglong2 AB1 = p[20], CD1 = p[30];
            ulonglong2 AB2 = p[40], CD2 = p[50];
            ulonglong2 AB3 = p[60], CD3 = p[70];
            ulonglong2 AB4 = p[80], CD4 = p[90];

            // identity-padded pair (last of last chunk): t2 reads a stale but
            // finite slot; it multiplies p01 = p11 = 0.
            float t1a = txa[2 * jj + 1], t2a = txa[2 * jj + 2];
            float t1b = txb[2 * jj + 1], t2b = txb[2 * jj + 2];
            uint64_t t1a2 = pack2(t1a, t1a), t2a2 = pack2(t2a, t2a);
            uint64_t t1b2 = pack2(t1b, t1b), t2b2 = pack2(t2b, t2b);
            float ca = t1a * t2a, cb = t1b * t2b;
            uint64_t ca2 = pack2(ca, ca), cb2 = pack2(cb, cb);

            // ---- shuffles ----
            uint64_t vla2[5], vlb2[5];
            #pragma unroll
            for (int q = 0; q < 5; q++) {
                float a0 = __shfl_sync(FULL, va, 2 * q,     16);
                float a1 = __shfl_sync(FULL, va, 2 * q + 1, 16);
                float b0 = __shfl_sync(FULL, vb, 2 * q,     16);
                float b1 = __shfl_sync(FULL, vb, 2 * q + 1, 16);
                vla2[q] = pack2(a0, a1);
                vlb2[q] = pack2(b0, b1);
            }

            // ---- packed math ----
            uint64_t wa2 = 0, wb2 = 0;
            {
                uint64_t ma, mb;
                ma = fma2(t1a2, AB0.y, AB0.x); mb = fma2(t1b2, AB0.y, AB0.x);
                ma = fma2(t2a2, CD0.x, ma);    mb = fma2(t2b2, CD0.x, mb);
                ma = fma2(ca2,  CD0.y, ma);    mb = fma2(cb2,  CD0.y, mb);
                wa2 = fma2(vla2[0], ma, wa2);  wb2 = fma2(vlb2[0], mb, wb2);
                ma = fma2(t1a2, AB1.y, AB1.x); mb = fma2(t1b2, AB1.y, AB1.x);
                ma = fma2(t2a2, CD1.x, ma);    mb = fma2(t2b2, CD1.x, mb);
                ma = fma2(ca2,  CD1.y, ma);    mb = fma2(cb2,  CD1.y, mb);
                wa2 = fma2(vla2[1], ma, wa2);  wb2 = fma2(vlb2[1], mb, wb2);
                ma = fma2(t1a2, AB2.y, AB2.x); mb = fma2(t1b2, AB2.y, AB2.x);
                ma = fma2(t2a2, CD2.x, ma);    mb = fma2(t2b2, CD2.x, mb);
                ma = fma2(ca2,  CD2.y, ma);    mb = fma2(cb2,  CD2.y, mb);
                wa2 = fma2(vla2[2], ma, wa2);  wb2 = fma2(vlb2[2], mb, wb2);
                ma = fma2(t1a2, AB3.y, AB3.x); mb = fma2(t1b2, AB3.y, AB3.x);
                ma = fma2(t2a2, CD3.x, ma);    mb = fma2(t2b2, CD3.x, mb);
                ma = fma2(ca2,  CD3.y, ma);    mb = fma2(cb2,  CD3.y, mb);
                wa2 = fma2(vla2[3], ma, wa2);  wb2 = fma2(vlb2[3], mb, wb2);
                ma = fma2(t1a2, AB4.y, AB4.x); mb = fma2(t1b2, AB4.y, AB4.x);
                ma = fma2(t2a2, CD4.x, ma);    mb = fma2(t2b2, CD4.x, mb);
                ma = fma2(ca2,  CD4.y, ma);    mb = fma2(cb2,  CD4.y, mb);
                wa2 = fma2(vla2[4], ma, wa2);  wb2 = fma2(vlb2[4], mb, wb2);
            }
            va = sum2(wa2);
            vb = sum2(wb2);
        }

        // exact power-of-2 rescale per batch
        {
            float ssa = act ? va * va : 0.0f;
            float ssb = act ? vb * vb : 0.0f;
            ssa += __shfl_xor_sync(FULL, ssa, 1, 16);
            ssb += __shfl_xor_sync(FULL, ssb, 1, 16);
            ssa += __shfl_xor_sync(FULL, ssa, 2, 16);
            ssb += __shfl_xor_sync(FULL, ssb, 2, 16);
            ssa += __shfl_xor_sync(FULL, ssa, 4, 16);
            ssb += __shfl_xor_sync(FULL, ssb, 4, 16);
            ssa += __shfl_xor_sync(FULL, ssa, 8, 16);
            ssb += __shfl_xor_sync(FULL, ssb, 8, 16);
            int sha = (((__float_as_int(ssa) >> 23) & 0xff) - 127) >> 1;
            int shb = (((__float_as_int(ssb) >> 23) & 0xff) - 127) >> 1;
            Ka += sha;
            Kb += shb;
            va *= __int_as_float((127 - sha) << 23);
            vb *= __int_as_float((127 - shb) << 23);
        }

        if (c + 1 < NCHUNK)
            asm volatile("cp.async.wait_group 0;" ::: "memory");
        __syncthreads();
    }

    // final norm + single log per batch
    float ssa = act ? va * va : 0.0f;
    float ssb = act ? vb * vb : 0.0f;
    ssa += __shfl_xor_sync(FULL, ssa, 1, 16);
    ssb += __shfl_xor_sync(FULL, ssb, 1, 16);
    ssa += __shfl_xor_sync(FULL, ssa, 2, 16);
    ssb += __shfl_xor_sync(FULL, ssb, 2, 16);
    ssa += __shfl_xor_sync(FULL, ssa, 4, 16);
    ssb += __shfl_xor_sync(FULL, ssb, 4, 16);
    ssa += __shfl_xor_sync(FULL, ssa, 8, 16);
    ssb += __shfl_xor_sync(FULL, ssb, 8, 16);
    float na = fmaxf(sqrtf(ssa), 1e-30f);
    float nb = fmaxf(sqrtf(ssb), 1e-30f);
    const float LN2 = 0.69314718055994531f;
    float lna = (float)Ka * LN2 + __logf(na);
    float lnb = (float)Kb * LN2 + __logf(nb);
    va *= (1.0f / na);
    vb *= (1.0f / nb);

    // logits[b,o] = sum_l v_l * cls[o,l] + lognorm   (lane h = class o)
    float cw[10];
    #pragma unroll
    for (int l = 0; l < 10; l++) cw[l] = __ldg(cls + hc * 10 + l);
    float acca = lna, accb = lnb;
    #pragma unroll
    for (int l = 0; l < 10; l++) {
        float vla = __shfl_sync(FULL, va, l, 16);
        float vlb = __shfl_sync(FULL, vb, l, 16);
        acca = fmaf(vla, cw[l], acca);
        accb = fmaf(vlb, cw[l], accb);
    }
    if (act) {
        out[(size_t)ba * 10 + h] = acca;
        out[(size_t)bb * 10 + h] = accb;
    }
}

// ---------------------------------------------------------------------------
extern "C" void kernel_launch(void* const* d_in, const int* in_sizes, int n_in,
                              void* d_out, int out_size) {
    const float* x     = (const float*)d_in[0];  // [2048, 784]
    const float* core0 = (const float*)d_in[1];  // [1, 2, 10]
    const float* cm    = (const float*)d_in[2];  // [783, 10, 2, 10]
    const float* cls   = (const float*)d_in[3];  // [10, 10]
    float* out = (float*)d_out;                  // [2048, 10]

    prep_pairs_kernel<<<NPAIR, 128>>>(cm);
    mps_chain_kernel<<<NBLOCK, THREADS>>>(x, core0, cls, out);
}